// round 9
// baseline (speedup 1.0000x reference)
#include <cuda_runtime.h>
#include <math.h>

#define BATCH 8
#define NPTS 2048
#define KPT 128
#define THREADS 256
#define NSLICE 32
#define SLEN 64

// dir0/dir1 partial min-d^2: g_part[slice][dir*16384 + b*2048 + row]
__device__ float g_part[NSLICE * 32768];
// dir3 partials: g_d3[quarter][b*128 + r]
__device__ float g_d3[4 * 1024];
// slots: [0..15] dir2 item sums, [16..23] per-batch small losses
__device__ float g_slots[24];
// per-block sums from pass2 + completion counter
__device__ float g_bsum[33];
__device__ unsigned int g_count;

__device__ __forceinline__ float block_reduce_256(float v, float* red) {
    const int tid = threadIdx.x;
    red[tid] = v;
    __syncthreads();
    #pragma unroll
    for (int s = THREADS / 2; s > 0; s >>= 1) {
        if (tid < s) red[tid] += red[tid + s];
        __syncthreads();
    }
    return red[0];
}

__global__ void __launch_bounds__(THREADS, 4)
passA(const float* __restrict__ pts,
      const float* __restrict__ recon,
      const float* __restrict__ kpt,
      const float* __restrict__ recon_delta,
      const float* __restrict__ pred_nocs,
      const float* __restrict__ pred_R,
      const float* __restrict__ pred_t,
      const float* __restrict__ pred_s,
      const float* __restrict__ gt_R,
      const float* __restrict__ gt_t,
      const float* __restrict__ gt_s) {
    __shared__ __align__(16) unsigned char s_buf[8192];
    __shared__ float s_red[THREADS];

    const int bid = blockIdx.x;
    const int tid = threadIdx.x;

    if (bid < 512) {
        // ===== heavy: dir0/dir1, 2048 rows (8/thread), 64-target slice =====
        const int dir = bid >> 8;
        const int b   = (bid >> 5) & 7;
        const int s   = bid & 31;

        const float* Q = (dir == 0 ? pts : recon) + (size_t)b * NPTS * 3;
        const float* T = (dir == 0 ? recon : pts) + (size_t)b * NPTS * 3 + s * SLEN * 3;

        float4* tile = (float4*)s_buf;  // (-2x, -2y, -2z, |s|^2) per target
        if (tid < SLEN) {
            float x = T[tid * 3 + 0];
            float y = T[tid * 3 + 1];
            float z = T[tid * 3 + 2];
            float w = fmaf(x, x, fmaf(y, y, z * z));
            tile[tid] = make_float4(-2.0f * x, -2.0f * y, -2.0f * z, w);
        }
        __syncthreads();

        // 8 query rows per thread, in registers
        float qx[8], qy[8], qz[8], q2[8];
        #pragma unroll
        for (int q = 0; q < 8; q++) {
            const int r = tid + 256 * q;
            qx[q] = Q[r * 3 + 0];
            qy[q] = Q[r * 3 + 1];
            qz[q] = Q[r * 3 + 2];
            q2[q] = fmaf(qx[q], qx[q], fmaf(qy[q], qy[q], qz[q] * qz[q]));
        }

        float m[8];
        #pragma unroll
        for (int q = 0; q < 8; q++) m[q] = 3.0e38f;

        #pragma unroll 4
        for (int t = 0; t < SLEN; t++) {
            const float4 sv = tile[t];
            #pragma unroll
            for (int q = 0; q < 8; q++) {
                float v = fmaf(sv.x, qx[q], fmaf(sv.y, qy[q], fmaf(sv.z, qz[q], sv.w)));
                m[q] = fminf(m[q], v);
            }
        }

        float* dst = g_part + (size_t)s * 32768 + dir * 16384 + b * 2048;
        #pragma unroll
        for (int q = 0; q < 8; q++) dst[tid + 256 * q] = q2[q] + m[q];
        return;
    }

    // ===== light items on blocks 512..567 (56 items) =====
    {
        const int id = bid - 512;
        if (id < 16) {
            // dir2: pts -> kpt, 1024-row half, full 128 targets
            const int b = id >> 1;
            const int half = id & 1;
            const float* Q = pts + (size_t)b * NPTS * 3;
            const float* T = kpt + (size_t)b * KPT * 3;
            float4* tile = (float4*)s_buf;
            if (tid < KPT) {
                float x = T[tid * 3 + 0];
                float y = T[tid * 3 + 1];
                float z = T[tid * 3 + 2];
                float w = fmaf(x, x, fmaf(y, y, z * z));
                tile[tid] = make_float4(-2.0f * x, -2.0f * y, -2.0f * z, w);
            }
            __syncthreads();

            const int rowbase = half * 1024;
            float sum = 0.0f;
            #pragma unroll
            for (int q = 0; q < 4; q++) {
                const int r = rowbase + tid + 256 * q;
                float qx = Q[r * 3 + 0];
                float qy = Q[r * 3 + 1];
                float qz = Q[r * 3 + 2];
                float q2 = fmaf(qx, qx, fmaf(qy, qy, qz * qz));
                float mm = 3.0e38f;
                #pragma unroll 8
                for (int t = 0; t < KPT; t++) {
                    float4 sv = tile[t];
                    float v = fmaf(sv.x, qx, fmaf(sv.y, qy, fmaf(sv.z, qz, sv.w)));
                    mm = fminf(mm, v);
                }
                sum += sqrtf(fmaxf(q2 + mm, 0.0f));
            }
            float tot = block_reduce_256(sum, s_red);
            if (tid == 0) g_slots[id] = tot * (0.5f / (BATCH * NPTS));
        } else if (id < 48) {
            // dir3: kpt -> pts, 512-target quarter -> partial
            const int j = id - 16;
            const int b = j >> 2;
            const int quarter = j & 3;
            const float* Q = kpt + (size_t)b * KPT * 3;
            const float* T = pts + (size_t)b * NPTS * 3 + quarter * 512 * 3;
            float4* tile = (float4*)s_buf;
            for (int jj = tid; jj < 512; jj += THREADS) {
                float x = T[jj * 3 + 0];
                float y = T[jj * 3 + 1];
                float z = T[jj * 3 + 2];
                float w = fmaf(x, x, fmaf(y, y, z * z));
                tile[jj] = make_float4(-2.0f * x, -2.0f * y, -2.0f * z, w);
            }
            __syncthreads();

            if (tid < KPT) {
                float qx = Q[tid * 3 + 0];
                float qy = Q[tid * 3 + 1];
                float qz = Q[tid * 3 + 2];
                float q2 = fmaf(qx, qx, fmaf(qy, qy, qz * qz));
                float mm = 3.0e38f;
                #pragma unroll 8
                for (int t = 0; t < 512; t++) {
                    float4 sv = tile[t];
                    float v = fmaf(sv.x, qx, fmaf(sv.y, qy, fmaf(sv.z, qz, sv.w)));
                    mm = fminf(mm, v);
                }
                g_d3[quarter * 1024 + b * KPT + tid] = q2 + mm;
            }
        } else {
            // smalls: pose + NOCS + diversity + delta per batch
            const int b = id - 48;
            float* sk = (float*)s_buf;
            const float* K = kpt + (size_t)b * KPT * 3;
            for (int i = tid; i < KPT * 3; i += THREADS) sk[i] = K[i];
            __syncthreads();

            float acc = 0.0f;
            const float invDiv = 1.0f / (float)(BATCH * KPT * KPT);
            for (int p = tid; p < KPT * KPT; p += THREADS) {
                const int i = p >> 7;
                const int jj = p & 127;
                float c;
                if (i == jj) {
                    c = 0.1f;
                } else {
                    float dx = sk[i * 3 + 0] - sk[jj * 3 + 0];
                    float dy = sk[i * 3 + 1] - sk[jj * 3 + 1];
                    float dz = sk[i * 3 + 2] - sk[jj * 3 + 2];
                    c = fminf(sqrtf(fmaf(dx, dx, fmaf(dy, dy, dz * dz))), 0.1f);
                }
                acc += c * invDiv;
            }

            if (tid < KPT) {
                const float* R = gt_R + (size_t)b * 9;
                const float t0 = gt_t[b * 3 + 0], t1 = gt_t[b * 3 + 1], t2 = gt_t[b * 3 + 2];
                const float s0 = gt_s[b * 3 + 0], s1 = gt_s[b * 3 + 1], s2 = gt_s[b * 3 + 2];
                const float scale = sqrtf(s0 * s0 + s1 * s1 + s2 * s2) + 1e-8f;
                const float inv = 1.0f / scale;
                const float px = (sk[tid * 3 + 0] - t0) * inv;
                const float py = (sk[tid * 3 + 1] - t1) * inv;
                const float pz = (sk[tid * 3 + 2] - t2) * inv;
                const float* pn = pred_nocs + ((size_t)b * KPT + tid) * 3;
                float sl = 0.0f;
                #pragma unroll
                for (int jj = 0; jj < 3; jj++) {
                    float g = px * R[jj] + py * R[3 + jj] + pz * R[6 + jj];
                    float d = fabsf(pn[jj] - g);
                    sl += (d > 0.1f) ? (d - 0.05f) : (d * d * 5.0f);
                }
                acc += sl * (1.0f / (float)(BATCH * KPT));
            }

            const float* D = recon_delta + (size_t)b * NPTS * 3;
            float dsum = 0.0f;
            for (int r = tid; r < NPTS; r += THREADS) {
                float x = D[r * 3 + 0];
                float y = D[r * 3 + 1];
                float z = D[r * 3 + 2];
                dsum += sqrtf(fmaf(x, x, fmaf(y, y, z * z)));
            }
            acc += dsum * (1.0f / (float)(BATCH * NPTS));

            float tot = block_reduce_256(acc, s_red);
            if (tid == 0) {
                const float* Rp = pred_R + (size_t)b * 9;
                const float* Rg = gt_R + (size_t)b * 9;
                float cs = 0.0f;
                #pragma unroll
                for (int jj = 0; jj < 3; jj++) {
                    float a0 = Rp[jj]     - Rg[jj];
                    float a1 = Rp[3 + jj] - Rg[3 + jj];
                    float a2 = Rp[6 + jj] - Rg[6 + jj];
                    cs += sqrtf(a0 * a0 + a1 * a1 + a2 * a2);
                }
                float dt0 = pred_t[b * 3 + 0] - gt_t[b * 3 + 0];
                float dt1 = pred_t[b * 3 + 1] - gt_t[b * 3 + 1];
                float dt2 = pred_t[b * 3 + 2] - gt_t[b * 3 + 2];
                float tn = sqrtf(dt0 * dt0 + dt1 * dt1 + dt2 * dt2);
                float ds0 = pred_s[b * 3 + 0] - gt_s[b * 3 + 0];
                float ds1 = pred_s[b * 3 + 1] - gt_s[b * 3 + 1];
                float ds2 = pred_s[b * 3 + 2] - gt_s[b * 3 + 2];
                float sn = sqrtf(ds0 * ds0 + ds1 * ds1 + ds2 * ds2);
                g_slots[16 + b] = tot
                                + cs * (1.0f / (3.0f * BATCH))
                                + tn * (1.0f / BATCH)
                                + sn * (1.0f / BATCH);
            }
        }
    }
}

// pass2: 33 blocks. Blocks 0..31 combine dir0/dir1 partials; block 32 does
// dir3 + slots. The LAST block to finish sums g_bsum into out[0] (deterministic:
// all inputs are fixed once all blocks completed; counter reset for graph replay).
__global__ void pass2(float* __restrict__ out) {
    __shared__ float red[THREADS];
    __shared__ unsigned int s_rank;
    const int bid = blockIdx.x;
    const int tid = threadIdx.x;
    float a = 0.0f;

    if (bid < 32) {
        // 1024 rows per block, 4 rows per thread (float4)
        const int row4 = bid * 1024 + tid * 4;
        float4 mm = make_float4(3.0e38f, 3.0e38f, 3.0e38f, 3.0e38f);
        #pragma unroll
        for (int s = 0; s < NSLICE; s++) {
            float4 p = *(const float4*)(g_part + (size_t)s * 32768 + row4);
            mm.x = fminf(mm.x, p.x);
            mm.y = fminf(mm.y, p.y);
            mm.z = fminf(mm.z, p.z);
            mm.w = fminf(mm.w, p.w);
        }
        a = (sqrtf(fmaxf(mm.x, 0.0f)) + sqrtf(fmaxf(mm.y, 0.0f))
           + sqrtf(fmaxf(mm.z, 0.0f)) + sqrtf(fmaxf(mm.w, 0.0f)))
          * (0.5f / (BATCH * NPTS));
    } else {
        #pragma unroll
        for (int q = 0; q < 4; q++) {
            const int idx = tid + 256 * q;
            float mm = fminf(fminf(g_d3[idx], g_d3[1024 + idx]),
                             fminf(g_d3[2048 + idx], g_d3[3072 + idx]));
            a += sqrtf(fmaxf(mm, 0.0f)) * (0.5f / (BATCH * KPT));
        }
        if (tid < 24) a += g_slots[tid];
    }

    red[tid] = a;
    __syncthreads();
    #pragma unroll
    for (int s = THREADS / 2; s > 0; s >>= 1) {
        if (tid < s) red[tid] += red[tid + s];
        __syncthreads();
    }

    if (tid == 0) {
        g_bsum[bid] = red[0];
        __threadfence();
        s_rank = atomicAdd(&g_count, 1u);
    }
    __syncthreads();

    if (s_rank == 32u) {  // last block to arrive
        __threadfence();
        float t = (tid < 33) ? g_bsum[tid] : 0.0f;
        red[tid] = t;
        __syncthreads();
        #pragma unroll
        for (int s = THREADS / 2; s > 0; s >>= 1) {
            if (tid < s) red[tid] += red[tid + s];
            __syncthreads();
        }
        if (tid == 0) {
            out[0] = red[0];
            g_count = 0;  // reset for next graph replay
        }
    }
}

extern "C" void kernel_launch(void* const* d_in, const int* in_sizes, int n_in,
                              void* d_out, int out_size) {
    const float* pts         = (const float*)d_in[0];
    const float* recon_delta = (const float*)d_in[1];
    const float* kpt         = (const float*)d_in[2];
    const float* recon       = (const float*)d_in[3];
    const float* pred_nocs   = (const float*)d_in[4];
    const float* pred_R      = (const float*)d_in[5];
    const float* pred_t      = (const float*)d_in[6];
    const float* pred_s      = (const float*)d_in[7];
    const float* gt_R        = (const float*)d_in[8];
    const float* gt_t        = (const float*)d_in[9];
    const float* gt_s        = (const float*)d_in[10];

    passA<<<568, THREADS>>>(pts, recon, kpt, recon_delta, pred_nocs,
                            pred_R, pred_t, pred_s, gt_R, gt_t, gt_s);
    pass2<<<33, THREADS>>>((float*)d_out);
}

// round 11
// speedup vs baseline: 1.0911x; 1.0911x over previous
#include <cuda_runtime.h>
#include <math.h>

#define BATCH 8
#define NPTS 2048
#define KPT 128
#define THREADS 256
#define NSLICE 32
#define SLEN 64

// Encoded min-d^2 accumulators. Encoding: u = ~__float_as_uint(max(d2,0)).
// For non-negative floats the bit pattern is monotone in the value, so the
// complement is anti-monotone: larger unsigned u == smaller d2, hence
// unsigned atomicMax == float min. All encoded values are >= 0x80000000,
// so the zero-initialized state (and post-pass2 reset) is the identity.
__device__ unsigned int g_min[2 * 16384];   // [dir*16384 + b*2048 + row]
__device__ unsigned int g_d3min[1024];      // [b*128 + r]
// slots: [0..15] dir2 item sums, [16..23] per-batch small losses
__device__ float g_slots[24];
// per-block sums from pass2 + completion counter
__device__ float g_bsum[33];
__device__ unsigned int g_count;

__device__ __forceinline__ unsigned int enc_min(float d2) {
    return ~__float_as_uint(fmaxf(d2, 0.0f));
}
__device__ __forceinline__ float dec_min(unsigned int u) {
    return __uint_as_float(~u);
}

__device__ __forceinline__ float block_reduce_256(float v, float* red) {
    const int tid = threadIdx.x;
    red[tid] = v;
    __syncthreads();
    #pragma unroll
    for (int s = THREADS / 2; s > 0; s >>= 1) {
        if (tid < s) red[tid] += red[tid + s];
        __syncthreads();
    }
    return red[0];
}

__global__ void __launch_bounds__(THREADS, 4)
passA(const float* __restrict__ pts,
      const float* __restrict__ recon,
      const float* __restrict__ kpt,
      const float* __restrict__ recon_delta,
      const float* __restrict__ pred_nocs,
      const float* __restrict__ pred_R,
      const float* __restrict__ pred_t,
      const float* __restrict__ pred_s,
      const float* __restrict__ gt_R,
      const float* __restrict__ gt_t,
      const float* __restrict__ gt_s) {
    __shared__ __align__(16) unsigned char s_buf[8192];
    __shared__ float s_red[THREADS];

    const int bid = blockIdx.x;
    const int tid = threadIdx.x;

    if (bid < 512) {
        // ===== heavy: dir0/dir1, 2048 rows (8/thread), 64-target slice =====
        const int dir = bid >> 8;
        const int b   = (bid >> 5) & 7;
        const int s   = bid & 31;

        const float* Q = (dir == 0 ? pts : recon) + (size_t)b * NPTS * 3;
        const float* T = (dir == 0 ? recon : pts) + (size_t)b * NPTS * 3 + s * SLEN * 3;

        float4* tile = (float4*)s_buf;  // (-2x, -2y, -2z, |s|^2) per target
        if (tid < SLEN) {
            float x = T[tid * 3 + 0];
            float y = T[tid * 3 + 1];
            float z = T[tid * 3 + 2];
            float w = fmaf(x, x, fmaf(y, y, z * z));
            tile[tid] = make_float4(-2.0f * x, -2.0f * y, -2.0f * z, w);
        }
        __syncthreads();

        // 8 query rows per thread, in registers
        float qx[8], qy[8], qz[8], q2[8];
        #pragma unroll
        for (int q = 0; q < 8; q++) {
            const int r = tid + 256 * q;
            qx[q] = Q[r * 3 + 0];
            qy[q] = Q[r * 3 + 1];
            qz[q] = Q[r * 3 + 2];
            q2[q] = fmaf(qx[q], qx[q], fmaf(qy[q], qy[q], qz[q] * qz[q]));
        }

        float m[8];
        #pragma unroll
        for (int q = 0; q < 8; q++) m[q] = 3.0e38f;

        #pragma unroll 4
        for (int t = 0; t < SLEN; t++) {
            const float4 sv = tile[t];
            #pragma unroll
            for (int q = 0; q < 8; q++) {
                float v = fmaf(sv.x, qx[q], fmaf(sv.y, qy[q], fmaf(sv.z, qz[q], sv.w)));
                m[q] = fminf(m[q], v);
            }
        }

        unsigned int* dst = g_min + dir * 16384 + b * 2048;
        #pragma unroll
        for (int q = 0; q < 8; q++)
            atomicMax(&dst[tid + 256 * q], enc_min(q2[q] + m[q]));
        return;
    }

    // ===== light items on blocks 512..567 (56 items) =====
    {
        const int id = bid - 512;
        if (id < 16) {
            // dir2: pts -> kpt, 1024-row half, full 128 targets (direct sum)
            const int b = id >> 1;
            const int half = id & 1;
            const float* Q = pts + (size_t)b * NPTS * 3;
            const float* T = kpt + (size_t)b * KPT * 3;
            float4* tile = (float4*)s_buf;
            if (tid < KPT) {
                float x = T[tid * 3 + 0];
                float y = T[tid * 3 + 1];
                float z = T[tid * 3 + 2];
                float w = fmaf(x, x, fmaf(y, y, z * z));
                tile[tid] = make_float4(-2.0f * x, -2.0f * y, -2.0f * z, w);
            }
            __syncthreads();

            const int rowbase = half * 1024;
            float sum = 0.0f;
            #pragma unroll
            for (int q = 0; q < 4; q++) {
                const int r = rowbase + tid + 256 * q;
                float qx = Q[r * 3 + 0];
                float qy = Q[r * 3 + 1];
                float qz = Q[r * 3 + 2];
                float q2 = fmaf(qx, qx, fmaf(qy, qy, qz * qz));
                float mm = 3.0e38f;
                #pragma unroll 8
                for (int t = 0; t < KPT; t++) {
                    float4 sv = tile[t];
                    float v = fmaf(sv.x, qx, fmaf(sv.y, qy, fmaf(sv.z, qz, sv.w)));
                    mm = fminf(mm, v);
                }
                sum += sqrtf(fmaxf(q2 + mm, 0.0f));
            }
            float tot = block_reduce_256(sum, s_red);
            if (tid == 0) g_slots[id] = tot * (0.5f / (BATCH * NPTS));
        } else if (id < 48) {
            // dir3: kpt -> pts, 512-target quarter -> atomic min partial
            const int j = id - 16;
            const int b = j >> 2;
            const int quarter = j & 3;
            const float* Q = kpt + (size_t)b * KPT * 3;
            const float* T = pts + (size_t)b * NPTS * 3 + quarter * 512 * 3;
            float4* tile = (float4*)s_buf;
            for (int jj = tid; jj < 512; jj += THREADS) {
                float x = T[jj * 3 + 0];
                float y = T[jj * 3 + 1];
                float z = T[jj * 3 + 2];
                float w = fmaf(x, x, fmaf(y, y, z * z));
                tile[jj] = make_float4(-2.0f * x, -2.0f * y, -2.0f * z, w);
            }
            __syncthreads();

            if (tid < KPT) {
                float qx = Q[tid * 3 + 0];
                float qy = Q[tid * 3 + 1];
                float qz = Q[tid * 3 + 2];
                float q2 = fmaf(qx, qx, fmaf(qy, qy, qz * qz));
                float mm = 3.0e38f;
                #pragma unroll 8
                for (int t = 0; t < 512; t++) {
                    float4 sv = tile[t];
                    float v = fmaf(sv.x, qx, fmaf(sv.y, qy, fmaf(sv.z, qz, sv.w)));
                    mm = fminf(mm, v);
                }
                atomicMax(&g_d3min[b * KPT + tid], enc_min(q2 + mm));
            }
        } else {
            // smalls: pose + NOCS + diversity + delta per batch
            const int b = id - 48;
            float* sk = (float*)s_buf;
            const float* K = kpt + (size_t)b * KPT * 3;
            for (int i = tid; i < KPT * 3; i += THREADS) sk[i] = K[i];
            __syncthreads();

            float acc = 0.0f;
            const float invDiv = 1.0f / (float)(BATCH * KPT * KPT);
            for (int p = tid; p < KPT * KPT; p += THREADS) {
                const int i = p >> 7;
                const int jj = p & 127;
                float c;
                if (i == jj) {
                    c = 0.1f;
                } else {
                    float dx = sk[i * 3 + 0] - sk[jj * 3 + 0];
                    float dy = sk[i * 3 + 1] - sk[jj * 3 + 1];
                    float dz = sk[i * 3 + 2] - sk[jj * 3 + 2];
                    c = fminf(sqrtf(fmaf(dx, dx, fmaf(dy, dy, dz * dz))), 0.1f);
                }
                acc += c * invDiv;
            }

            if (tid < KPT) {
                const float* R = gt_R + (size_t)b * 9;
                const float t0 = gt_t[b * 3 + 0], t1 = gt_t[b * 3 + 1], t2 = gt_t[b * 3 + 2];
                const float s0 = gt_s[b * 3 + 0], s1 = gt_s[b * 3 + 1], s2 = gt_s[b * 3 + 2];
                const float scale = sqrtf(s0 * s0 + s1 * s1 + s2 * s2) + 1e-8f;
                const float inv = 1.0f / scale;
                const float px = (sk[tid * 3 + 0] - t0) * inv;
                const float py = (sk[tid * 3 + 1] - t1) * inv;
                const float pz = (sk[tid * 3 + 2] - t2) * inv;
                const float* pn = pred_nocs + ((size_t)b * KPT + tid) * 3;
                float sl = 0.0f;
                #pragma unroll
                for (int jj = 0; jj < 3; jj++) {
                    float g = px * R[jj] + py * R[3 + jj] + pz * R[6 + jj];
                    float d = fabsf(pn[jj] - g);
                    sl += (d > 0.1f) ? (d - 0.05f) : (d * d * 5.0f);
                }
                acc += sl * (1.0f / (float)(BATCH * KPT));
            }

            const float* D = recon_delta + (size_t)b * NPTS * 3;
            float dsum = 0.0f;
            for (int r = tid; r < NPTS; r += THREADS) {
                float x = D[r * 3 + 0];
                float y = D[r * 3 + 1];
                float z = D[r * 3 + 2];
                dsum += sqrtf(fmaf(x, x, fmaf(y, y, z * z)));
            }
            acc += dsum * (1.0f / (float)(BATCH * NPTS));

            float tot = block_reduce_256(acc, s_red);
            if (tid == 0) {
                const float* Rp = pred_R + (size_t)b * 9;
                const float* Rg = gt_R + (size_t)b * 9;
                float cs = 0.0f;
                #pragma unroll
                for (int jj = 0; jj < 3; jj++) {
                    float a0 = Rp[jj]     - Rg[jj];
                    float a1 = Rp[3 + jj] - Rg[3 + jj];
                    float a2 = Rp[6 + jj] - Rg[6 + jj];
                    cs += sqrtf(a0 * a0 + a1 * a1 + a2 * a2);
                }
                float dt0 = pred_t[b * 3 + 0] - gt_t[b * 3 + 0];
                float dt1 = pred_t[b * 3 + 1] - gt_t[b * 3 + 1];
                float dt2 = pred_t[b * 3 + 2] - gt_t[b * 3 + 2];
                float tn = sqrtf(dt0 * dt0 + dt1 * dt1 + dt2 * dt2);
                float ds0 = pred_s[b * 3 + 0] - gt_s[b * 3 + 0];
                float ds1 = pred_s[b * 3 + 1] - gt_s[b * 3 + 1];
                float ds2 = pred_s[b * 3 + 2] - gt_s[b * 3 + 2];
                float sn = sqrtf(ds0 * ds0 + ds1 * ds1 + ds2 * ds2);
                g_slots[16 + b] = tot
                                + cs * (1.0f / (3.0f * BATCH))
                                + tn * (1.0f / BATCH)
                                + sn * (1.0f / BATCH);
            }
        }
    }
}

// pass2: 33 blocks. Blocks 0..31 decode+sum 1024 g_min rows each; block 32
// handles dir3 + slots. Each block RESETS the cells it consumed back to 0
// (the atomicMax identity) so the graph can replay. The last block to finish
// sums g_bsum into out[0] (deterministic).
__global__ void pass2(float* __restrict__ out) {
    __shared__ float red[THREADS];
    __shared__ unsigned int s_rank;
    const int bid = blockIdx.x;
    const int tid = threadIdx.x;
    float a = 0.0f;

    if (bid < 32) {
        const int idx4 = bid * 1024 + tid * 4;
        uint4 u = *(const uint4*)(g_min + idx4);
        *(uint4*)(g_min + idx4) = make_uint4(0u, 0u, 0u, 0u);
        a = (sqrtf(dec_min(u.x)) + sqrtf(dec_min(u.y))
           + sqrtf(dec_min(u.z)) + sqrtf(dec_min(u.w)))
          * (0.5f / (BATCH * NPTS));
    } else {
        const int idx4 = tid * 4;
        uint4 u = *(const uint4*)(g_d3min + idx4);
        *(uint4*)(g_d3min + idx4) = make_uint4(0u, 0u, 0u, 0u);
        a = (sqrtf(dec_min(u.x)) + sqrtf(dec_min(u.y))
           + sqrtf(dec_min(u.z)) + sqrtf(dec_min(u.w)))
          * (0.5f / (BATCH * KPT));
        if (tid < 24) a += g_slots[tid];
    }

    red[tid] = a;
    __syncthreads();
    #pragma unroll
    for (int s = THREADS / 2; s > 0; s >>= 1) {
        if (tid < s) red[tid] += red[tid + s];
        __syncthreads();
    }

    if (tid == 0) {
        g_bsum[bid] = red[0];
        __threadfence();
        s_rank = atomicAdd(&g_count, 1u);
    }
    __syncthreads();

    if (s_rank == 32u) {  // last block to arrive
        __threadfence();
        float t = (tid < 33) ? g_bsum[tid] : 0.0f;
        red[tid] = t;
        __syncthreads();
        #pragma unroll
        for (int s = THREADS / 2; s > 0; s >>= 1) {
            if (tid < s) red[tid] += red[tid + s];
            __syncthreads();
        }
        if (tid == 0) {
            out[0] = red[0];
            g_count = 0;  // reset for next graph replay
        }
    }
}

extern "C" void kernel_launch(void* const* d_in, const int* in_sizes, int n_in,
                              void* d_out, int out_size) {
    const float* pts         = (const float*)d_in[0];
    const float* recon_delta = (const float*)d_in[1];
    const float* kpt         = (const float*)d_in[2];
    const float* recon       = (const float*)d_in[3];
    const float* pred_nocs   = (const float*)d_in[4];
    const float* pred_R      = (const float*)d_in[5];
    const float* pred_t      = (const float*)d_in[6];
    const float* pred_s      = (const float*)d_in[7];
    const float* gt_R        = (const float*)d_in[8];
    const float* gt_t        = (const float*)d_in[9];
    const float* gt_s        = (const float*)d_in[10];

    passA<<<568, THREADS>>>(pts, recon, kpt, recon_delta, pred_nocs,
                            pred_R, pred_t, pred_s, gt_R, gt_t, gt_s);
    pass2<<<33, THREADS>>>((float*)d_out);
}